// round 10
// baseline (speedup 1.0000x reference)
#include <cuda_runtime.h>
#include <cuda_bf16.h>
#include <math.h>
#include <stdint.h>

// Shapes (fixed): B*N=6400 rows, K=1024 noise, D=64, V=1e6.
#define DIM        64
#define K_NOISE    1024
#define ROWS_TOT   6400
#define MT         128                 // M tile (rows per CTA)
#define NT         128                 // N tile (noise cols per CTA)
#define A_BYTES    (MT * 128)          // 16 KB
#define B_BYTES    (NT * 128)          // 16 KB
#define GRID_M     (ROWS_TOT / MT)     // 50
#define GRID_N     (K_NOISE / NT)      // 8
#define NBLOCKS    (GRID_M * GRID_N)   // 400
#define NTHREADS   256
#define TROWS      (MT / GRID_N)       // 16 target rows per CTA
#define LOG2E      1.4426950408889634f

// Last-block reduction scratch (device globals: allocation-free)
__device__ float        g_partial[NBLOCKS];
__device__ unsigned int g_count = 0;

// ---------------------------------------------------------------------------
// helpers
// ---------------------------------------------------------------------------
static __device__ __forceinline__ uint32_t smem_u32(const void* p) {
    uint32_t a;
    asm("{ .reg .u64 t; cvta.to.shared.u64 t, %1; cvt.u32.u64 %0, t; }"
        : "=r"(a) : "l"(p));
    return a;
}

static __device__ __forceinline__ void ldsm_x4(uint32_t* r, uint32_t addr) {
    asm volatile("ldmatrix.sync.aligned.m8n8.x4.shared.b16 {%0,%1,%2,%3}, [%4];"
                 : "=r"(r[0]), "=r"(r[1]), "=r"(r[2]), "=r"(r[3]) : "r"(addr));
}

static __device__ __forceinline__ void mma16816(float* d, const uint32_t* a,
                                                const uint32_t* b) {
    asm volatile(
        "mma.sync.aligned.m16n8k16.row.col.f32.bf16.bf16.f32 "
        "{%0,%1,%2,%3}, {%4,%5,%6,%7}, {%8,%9}, {%0,%1,%2,%3};"
        : "+f"(d[0]), "+f"(d[1]), "+f"(d[2]), "+f"(d[3])
        : "r"(a[0]), "r"(a[1]), "r"(a[2]), "r"(a[3]), "r"(b[0]), "r"(b[1]));
}

// Robust softplus for the target term only (x can be any sign/magnitude).
__device__ __forceinline__ float softplus_full(float x)
{
    if (x > 8.0f) return x + __expf(-x);
    float z = __expf(x);
    if (z < 0.015625f) return z * fmaf(z, fmaf(z, 0.33333334f, -0.5f), 1.0f);
    return __logf(1.0f + z);
}

// Noise-term softplus accumulate, exp2 form: cl = c*log2e precomputed, so
// z = 2^(s*log2e - cl) = e^(s-c) << 1 always; softplus ~= z - z^2/2.
// 4 issue slots: FFMA + MUFU + 2 FMA, branch-free.
__device__ __forceinline__ float sp_noise2(float s, float cl, float acc)
{
    float z = exp2f(fmaf(s, LOG2E, -cl));
    return fmaf(z, fmaf(z, -0.5f, 1.0f), acc);
}

// convert 8 f32 (two float4) -> 8 bf16 packed in a uint4
static __device__ __forceinline__ uint4 pack8_bf16(float4 a, float4 b)
{
    __nv_bfloat162 h0 = __floats2bfloat162_rn(a.x, a.y);
    __nv_bfloat162 h1 = __floats2bfloat162_rn(a.z, a.w);
    __nv_bfloat162 h2 = __floats2bfloat162_rn(b.x, b.y);
    __nv_bfloat162 h3 = __floats2bfloat162_rn(b.z, b.w);
    uint4 p;
    p.x = *(uint32_t*)&h0; p.y = *(uint32_t*)&h1;
    p.z = *(uint32_t*)&h2; p.w = *(uint32_t*)&h3;
    return p;
}

// ---------------------------------------------------------------------------
// Fused NCE kernel, single launch. One CTA = 128 rows x 128 noise via
// mma.sync bf16; 256 threads / 8 warps in 4(M) x 2(N), two 32-col passes.
// Register-lean (target gather fully after mainloop) for 4 CTAs/SM.
// ---------------------------------------------------------------------------
__global__ void __launch_bounds__(NTHREADS, 4)
nce_fused_kernel(const int* __restrict__ target,
                 const float* __restrict__ input,
                 const float* __restrict__ embs,
                 const int* __restrict__ noise_samples,
                 const float* __restrict__ logprob_noise,
                 float norm_c, float inv_rows, float* __restrict__ d_out)
{
    __shared__ __align__(1024) char s_a[A_BYTES];   // 16 KB A (bf16 SW128)
    __shared__ __align__(1024) char s_b[B_BYTES];   // 16 KB B (bf16 SW128)
    __shared__ float s_c[NT];                       // c_k * log2e
    __shared__ float s_red[8];
    __shared__ int   s_last;

    const int tid    = threadIdx.x;
    const int lane   = tid & 31;
    const int wid    = tid >> 5;
    const int warp_m = wid & 3;        // 4 warps over M: 32 rows each
    const int warp_n = wid >> 2;       // 2 warps over N: 64 cols each
    const int bm     = blockIdx.x;
    const int bn     = blockIdx.y;

    // ---- early: only the target INDEX (1 register held across mainloop) ----
    int tgt_idx = 0;
    const bool has_tgt = (tid < TROWS);
    const int  trow = bm * MT + bn * TROWS + tid;
    if (has_tgt) tgt_idx = __ldg(&target[trow]);

    // ---- staging addresses (thread-invariant swizzle part) ----
    const int rgrp = tid >> 3;          // 0..31
    const int cchk = tid & 7;
    const uint32_t sw_thread =
        (uint32_t)rgrp * 128 + ((uint32_t)((rgrp & 7) ^ cchk) << 4);

    // --- stage in 2 batches (8 x float4 live regs each) ---
    {
        char* dstA = s_a + sw_thread;
        char* dstB = s_b + sw_thread;
        const float4* srcA = (const float4*)(input
            + (size_t)(bm * MT + rgrp) * DIM + cchk * 8);
#pragma unroll
        for (int h = 0; h < 2; h++) {
            float4 a0[2], a1[2], b0[2], b1[2];
            int nidx[2];
#pragma unroll
            for (int i = 0; i < 2; i++) {
                int ii = h * 2 + i;
                a0[i] = srcA[ii * 512];          // ii*32 rows * 16 f4/row
                a1[i] = srcA[ii * 512 + 1];
                nidx[i] = noise_samples[bn * NT + ii * 32 + rgrp];
            }
#pragma unroll
            for (int i = 0; i < 2; i++) {
                const float4* srcB = (const float4*)(embs
                    + (size_t)nidx[i] * DIM + cchk * 8);
                b0[i] = srcB[0];
                b1[i] = srcB[1];
            }
#pragma unroll
            for (int i = 0; i < 2; i++) {
                int ii = h * 2 + i;
                *(uint4*)(dstA + ii * 4096) = pack8_bf16(a0[i], a1[i]);
                *(uint4*)(dstB + ii * 4096) = pack8_bf16(b0[i], b1[i]);
            }
        }
    }
    if (tid < NT) {
        int it = noise_samples[bn * NT + tid];
        s_c[tid] = (norm_c + logprob_noise[it]) * LOG2E;
    }
    __syncthreads();

    // ---- LDSM base addresses (XOR-folded SW128) ----
    const uint32_t r7 = lane & 7;
    const uint32_t a_base0 = smem_u32(s_a)
        + (((uint32_t)(warp_m * 32 + (lane & 15)) * 128)
           ^ (r7 << 4) ^ ((uint32_t)(lane >> 4) << 4));
    const uint32_t b_base0 = smem_u32(s_b)
        + (((uint32_t)(warp_n * 64 + (lane & 7) + ((lane >> 4) << 3)) * 128)
           ^ (r7 << 4) ^ ((uint32_t)((lane >> 3) & 1) << 4));

    float loc0 = 0.0f, loc1 = 0.0f, loc2 = 0.0f, loc3 = 0.0f;

    // --- two 32-col passes per warp ---
#pragma unroll
    for (int np = 0; np < 2; np++) {
        float acc[2][4][4] = {};
#pragma unroll
        for (int k = 0; k < 4; k++) {           // K = 4 x k16
            uint32_t afr[2][4];
#pragma unroll
            for (int mi = 0; mi < 2; mi++)
                ldsm_x4(afr[mi], (a_base0 + mi * 2048) ^ (k << 5));
            uint32_t bfr[4][2];
#pragma unroll
            for (int nj = 0; nj < 2; nj++) {
                uint32_t b4[4];
                ldsm_x4(b4, (b_base0 + np * 4096 + nj * 2048) ^ (k << 5));
                bfr[nj * 2][0]     = b4[0]; bfr[nj * 2][1]     = b4[1];
                bfr[nj * 2 + 1][0] = b4[2]; bfr[nj * 2 + 1][1] = b4[3];
            }
#pragma unroll
            for (int mi = 0; mi < 2; mi++)
#pragma unroll
                for (int ni = 0; ni < 4; ni++)
                    mma16816(acc[mi][ni], afr[mi], bfr[ni]);
        }
        // epilogue for this pass: exp2-form, 4 independent chains
#pragma unroll
        for (int ni = 0; ni < 4; ni++) {
            int col = warp_n * 64 + np * 32 + ni * 8 + (lane & 3) * 2;
            float2 c01 = *(const float2*)&s_c[col];
#pragma unroll
            for (int mi = 0; mi < 2; mi++) {
                loc0 = sp_noise2(acc[mi][ni][0], c01.x, loc0);
                loc1 = sp_noise2(acc[mi][ni][1], c01.y, loc1);
                loc2 = sp_noise2(acc[mi][ni][2], c01.x, loc2);
                loc3 = sp_noise2(acc[mi][ni][3], c01.y, loc3);
            }
        }
    }
    float local = (loc0 + loc1) + (loc2 + loc3);

    // ---- target term (exact f32), after mainloop; tgt_idx arrived long ago ----
    if (has_tgt) {
        const float4* ti = (const float4*)(input + (size_t)trow * DIM);
        const float4* te = (const float4*)(embs + (size_t)tgt_idx * DIM);
        float tgt_lpn = __ldg(&logprob_noise[tgt_idx]);
        float acc = 0.0f;
#pragma unroll
        for (int i = 0; i < 4; i++) {
            float4 x = __ldg(&ti[i]), e = __ldg(&te[i]);
            acc = fmaf(x.x, e.x, fmaf(x.y, e.y, fmaf(x.z, e.z, fmaf(x.w, e.w, acc))));
        }
        float xt = acc - norm_c - tgt_lpn;
        local += softplus_full(-xt);
    }

    // --- block reduction ---
#pragma unroll
    for (int o = 16; o; o >>= 1)
        local += __shfl_xor_sync(0xffffffffu, local, o);
    if (lane == 0) s_red[wid] = local;
    __syncthreads();

    // --- last-block global reduction (single launch, graph-replay safe) ---
    const int bid = blockIdx.y * GRID_M + blockIdx.x;
    if (tid == 0) {
        float blk = 0.0f;
#pragma unroll
        for (int w = 0; w < 8; w++) blk += s_red[w];
        g_partial[bid] = blk;
        __threadfence();
        unsigned int old = atomicAdd(&g_count, 1u);
        s_last = (old == NBLOCKS - 1);
        if (s_last) __threadfence();
    }
    __syncthreads();
    if (s_last) {
        float v = 0.0f;
        for (int j = tid; j < NBLOCKS; j += NTHREADS)   // fixed order: deterministic
            v += g_partial[j];
#pragma unroll
        for (int o = 16; o; o >>= 1)
            v += __shfl_xor_sync(0xffffffffu, v, o);
        if (lane == 0) s_red[wid] = v;
        __syncthreads();
        if (tid == 0) {
            float s = 0.0f;
#pragma unroll
            for (int w = 0; w < 8; w++) s += s_red[w];
            d_out[0] = s * inv_rows;
            g_count = 0;                                // reset for next replay
        }
    }
}

// ---------------------------------------------------------------------------
// Launch. Inputs (metadata order): target i32[6400], input f32[6400*64],
// embs f32[1e6*64], noise_samples i32[1024], logprob_noise f32[1e6].
// Output: f32[1] (mean loss).
// ---------------------------------------------------------------------------
extern "C" void kernel_launch(void* const* d_in, const int* in_sizes, int n_in,
                              void* d_out, int out_size)
{
    const int*   target = (const int*)d_in[0];
    const float* input  = (const float*)d_in[1];
    const float* embs   = (const float*)d_in[2];
    const int*   noise  = (const int*)d_in[3];
    const float* lpn    = (const float*)d_in[4];
    float*       out    = (float*)d_out;

    const int rows = in_sizes[0];                              // 6400
    const float norm_c = logf((float)in_sizes[4]) + logf((float)in_sizes[3]);

    dim3 grid(GRID_M, GRID_N);                                 // 50 x 8
    nce_fused_kernel<<<grid, NTHREADS>>>(target, input, embs, noise, lpn,
                                         norm_c, 1.0f / (float)rows, out);
}

// round 11
// speedup vs baseline: 1.2959x; 1.2959x over previous
#include <cuda_runtime.h>
#include <cuda_bf16.h>
#include <math.h>
#include <stdint.h>

// Shapes (fixed): B*N=6400 rows, K=1024 noise, D=64, V=1e6.
#define DIM        64
#define K_NOISE    1024
#define ROWS_TOT   6400
#define MT         128                 // M tile (rows per CTA)
#define NT         128                 // N tile (noise cols per CTA)
#define A_BYTES    (MT * 128)          // 16 KB
#define B_BYTES    (NT * 128)          // 16 KB
#define GRID_M     (ROWS_TOT / MT)     // 50
#define GRID_N     (K_NOISE / NT)      // 8
#define NTHREADS   256
#define TROWS      (MT / GRID_N)       // 16 target rows per CTA
#define LOG2E      1.4426950408889634f

// ---------------------------------------------------------------------------
// helpers
// ---------------------------------------------------------------------------
static __device__ __forceinline__ uint32_t smem_u32(const void* p) {
    uint32_t a;
    asm("{ .reg .u64 t; cvta.to.shared.u64 t, %1; cvt.u32.u64 %0, t; }"
        : "=r"(a) : "l"(p));
    return a;
}

static __device__ __forceinline__ void ldsm_x4(uint32_t* r, uint32_t addr) {
    asm volatile("ldmatrix.sync.aligned.m8n8.x4.shared.b16 {%0,%1,%2,%3}, [%4];"
                 : "=r"(r[0]), "=r"(r[1]), "=r"(r[2]), "=r"(r[3]) : "r"(addr));
}

static __device__ __forceinline__ void mma16816(float* d, const uint32_t* a,
                                                const uint32_t* b) {
    asm volatile(
        "mma.sync.aligned.m16n8k16.row.col.f32.bf16.bf16.f32 "
        "{%0,%1,%2,%3}, {%4,%5,%6,%7}, {%8,%9}, {%0,%1,%2,%3};"
        : "+f"(d[0]), "+f"(d[1]), "+f"(d[2]), "+f"(d[3])
        : "r"(a[0]), "r"(a[1]), "r"(a[2]), "r"(a[3]), "r"(b[0]), "r"(b[1]));
}

// Robust softplus for the target term only (x can be any sign/magnitude).
__device__ __forceinline__ float softplus_full(float x)
{
    if (x > 8.0f) return x + __expf(-x);
    float z = __expf(x);
    if (z < 0.015625f) return z * fmaf(z, fmaf(z, 0.33333334f, -0.5f), 1.0f);
    return __logf(1.0f + z);
}

// Noise-term softplus accumulate, exp2 form: cl = c*log2e precomputed, so
// z = 2^(s*log2e - cl) = e^(s-c) << 1 always; softplus ~= z - z^2/2.
// 4 issue slots: FFMA + MUFU + 2 FMA, branch-free.
__device__ __forceinline__ float sp_noise2(float s, float cl, float acc)
{
    float z = exp2f(fmaf(s, LOG2E, -cl));
    return fmaf(z, fmaf(z, -0.5f, 1.0f), acc);
}

// convert 8 f32 (two float4) -> 8 bf16 packed in a uint4
static __device__ __forceinline__ uint4 pack8_bf16(float4 a, float4 b)
{
    __nv_bfloat162 h0 = __floats2bfloat162_rn(a.x, a.y);
    __nv_bfloat162 h1 = __floats2bfloat162_rn(a.z, a.w);
    __nv_bfloat162 h2 = __floats2bfloat162_rn(b.x, b.y);
    __nv_bfloat162 h3 = __floats2bfloat162_rn(b.z, b.w);
    uint4 p;
    p.x = *(uint32_t*)&h0; p.y = *(uint32_t*)&h1;
    p.z = *(uint32_t*)&h2; p.w = *(uint32_t*)&h3;
    return p;
}

// ---------------------------------------------------------------------------
// Tiny init kernel: zero the scalar output (stream-ordered before main).
// ---------------------------------------------------------------------------
__global__ void zero_kernel(float* __restrict__ d_out) { d_out[0] = 0.0f; }

// ---------------------------------------------------------------------------
// Fused NCE kernel: one CTA = 128 rows x 128 noise via mma.sync bf16.
//   grid = (50, 8) = 400 CTAs, 256 threads / 8 warps in 4(M) x 2(N);
//   each warp 32x64 as two 32-col passes. Max-MLP staging; target gather
//   split around the mainloop (index early, row prefetched post-barrier,
//   dot after MMA).
// ---------------------------------------------------------------------------
__global__ void __launch_bounds__(NTHREADS, 3)
nce_fused_kernel(const int* __restrict__ target,
                 const float* __restrict__ input,
                 const float* __restrict__ embs,
                 const int* __restrict__ noise_samples,
                 const float* __restrict__ logprob_noise,
                 float norm_c, float inv_rows, float* __restrict__ d_out)
{
    __shared__ __align__(1024) char s_a[A_BYTES];   // 16 KB A (bf16 SW128)
    __shared__ __align__(1024) char s_b[B_BYTES];   // 16 KB B (bf16 SW128)
    __shared__ float s_c[NT];                       // c_k * log2e
    __shared__ float s_red[8];

    const int tid    = threadIdx.x;
    const int lane   = tid & 31;
    const int wid    = tid >> 5;
    const int warp_m = wid & 3;        // 4 warps over M: 32 rows each
    const int warp_n = wid >> 2;       // 2 warps over N: 64 cols each
    const int bm     = blockIdx.x;
    const int bn     = blockIdx.y;

    // ---- early: kick off the target-index load (16 rows per CTA) ----
    int tgt_idx = 0;
    const bool has_tgt = (tid < TROWS);
    const int  trow = bm * MT + bn * TROWS + tid;
    if (has_tgt) tgt_idx = __ldg(&target[trow]);    // arrives during staging

    // ---- staging addresses (thread-invariant swizzle part) ----
    // rgrp = tid>>3 (0..31), cchk = tid&7; row_i = i*32 + rgrp keeps row&7
    // fixed, so the swizzled smem offset is sw_thread + i*4096.
    const int rgrp = tid >> 3;
    const int cchk = tid & 7;
    const uint32_t sw_thread =
        (uint32_t)rgrp * 128 + ((uint32_t)((rgrp & 7) ^ cchk) << 4);

    // --- issue ALL staging loads first (max MLP), then convert+store ---
    float4 a0[4], a1[4];                 // A: 4 chunks (rows rgrp + i*32)
    {
        const float4* src = (const float4*)(input
            + (size_t)(bm * MT + rgrp) * DIM + cchk * 8);
#pragma unroll
        for (int i = 0; i < 4; i++) {
            a0[i] = src[i * 16 * DIM / 4 * 2];      // i*32 rows = i*32*64 f32
            a1[i] = src[i * 16 * DIM / 4 * 2 + 1];
        }
    }
    int nidx[4];
#pragma unroll
    for (int i = 0; i < 4; i++)
        nidx[i] = noise_samples[bn * NT + i * 32 + rgrp];
    float4 b0[4], b1[4];
#pragma unroll
    for (int i = 0; i < 4; i++) {
        const float4* src = (const float4*)(embs + (size_t)nidx[i] * DIM + cchk * 8);
        b0[i] = src[0];
        b1[i] = src[1];
    }
    {
        char* dstA = s_a + sw_thread;
        char* dstB = s_b + sw_thread;
#pragma unroll
        for (int i = 0; i < 4; i++) {
            *(uint4*)(dstA + i * 4096) = pack8_bf16(a0[i], a1[i]);
            *(uint4*)(dstB + i * 4096) = pack8_bf16(b0[i], b1[i]);
        }
    }
    if (tid < NT) {
        int it = noise_samples[bn * NT + tid];
        s_c[tid] = (norm_c + logprob_noise[it]) * LOG2E;
    }
    __syncthreads();

    // ---- start the dependent target row load NOW; consume after mainloop ----
    float4 te_reg[4];
    float  tgt_lpn = 0.0f;
    if (has_tgt) {
        const float4* te = (const float4*)(embs + (size_t)tgt_idx * DIM);
#pragma unroll
        for (int i = 0; i < 4; i++) te_reg[i] = __ldg(&te[i]);
        tgt_lpn = __ldg(&logprob_noise[tgt_idx]);
    }

    // ---- LDSM base addresses (XOR-folded SW128) ----
    const uint32_t r7 = lane & 7;
    const uint32_t a_base0 = smem_u32(s_a)
        + (((uint32_t)(warp_m * 32 + (lane & 15)) * 128)
           ^ (r7 << 4) ^ ((uint32_t)(lane >> 4) << 4));
    const uint32_t b_base0 = smem_u32(s_b)
        + (((uint32_t)(warp_n * 64 + (lane & 7) + ((lane >> 4) << 3)) * 128)
           ^ (r7 << 4) ^ ((uint32_t)((lane >> 3) & 1) << 4));

    float loc0 = 0.0f, loc1 = 0.0f, loc2 = 0.0f, loc3 = 0.0f;

    // --- two 32-col passes per warp ---
#pragma unroll
    for (int np = 0; np < 2; np++) {
        float acc[2][4][4] = {};
#pragma unroll
        for (int k = 0; k < 4; k++) {           // K = 4 x k16
            uint32_t afr[2][4];
#pragma unroll
            for (int mi = 0; mi < 2; mi++)
                ldsm_x4(afr[mi], (a_base0 + mi * 2048) ^ (k << 5));
            uint32_t bfr[4][2];
#pragma unroll
            for (int nj = 0; nj < 2; nj++) {
                uint32_t b4[4];
                ldsm_x4(b4, (b_base0 + np * 4096 + nj * 2048) ^ (k << 5));
                bfr[nj * 2][0]     = b4[0]; bfr[nj * 2][1]     = b4[1];
                bfr[nj * 2 + 1][0] = b4[2]; bfr[nj * 2 + 1][1] = b4[3];
            }
#pragma unroll
            for (int mi = 0; mi < 2; mi++)
#pragma unroll
                for (int ni = 0; ni < 4; ni++)
                    mma16816(acc[mi][ni], afr[mi], bfr[ni]);
        }
        // epilogue for this pass: exp2-form, 4 independent chains
#pragma unroll
        for (int ni = 0; ni < 4; ni++) {
            int col = warp_n * 64 + np * 32 + ni * 8 + (lane & 3) * 2;
            float2 c01 = *(const float2*)&s_c[col];
#pragma unroll
            for (int mi = 0; mi < 2; mi++) {
                loc0 = sp_noise2(acc[mi][ni][0], c01.x, loc0);
                loc1 = sp_noise2(acc[mi][ni][1], c01.y, loc1);
                loc2 = sp_noise2(acc[mi][ni][2], c01.x, loc2);
                loc3 = sp_noise2(acc[mi][ni][3], c01.y, loc3);
            }
        }
    }
    float local = (loc0 + loc1) + (loc2 + loc3);

    // ---- deferred target term (exact f32; loads long since arrived) ----
    if (has_tgt) {
        const float4* ti = (const float4*)(input + (size_t)trow * DIM);
        float acc = 0.0f;
#pragma unroll
        for (int i = 0; i < 4; i++) {
            float4 x = ti[i], e = te_reg[i];
            acc = fmaf(x.x, e.x, fmaf(x.y, e.y, fmaf(x.z, e.z, fmaf(x.w, e.w, acc))));
        }
        float xt = acc - norm_c - tgt_lpn;
        local += softplus_full(-xt);
    }

    // --- block reduction + one atomicAdd per CTA ---
#pragma unroll
    for (int o = 16; o; o >>= 1)
        local += __shfl_xor_sync(0xffffffffu, local, o);
    if (lane == 0) s_red[wid] = local;
    __syncthreads();
    if (tid == 0) {
        float s = 0.0f;
#pragma unroll
        for (int w = 0; w < 8; w++) s += s_red[w];
        atomicAdd(d_out, s * inv_rows);
    }
}

// ---------------------------------------------------------------------------
// Launch. Inputs (metadata order): target i32[6400], input f32[6400*64],
// embs f32[1e6*64], noise_samples i32[1024], logprob_noise f32[1e6].
// Output: f32[1] (mean loss).
// ---------------------------------------------------------------------------
extern "C" void kernel_launch(void* const* d_in, const int* in_sizes, int n_in,
                              void* d_out, int out_size)
{
    const int*   target = (const int*)d_in[0];
    const float* input  = (const float*)d_in[1];
    const float* embs   = (const float*)d_in[2];
    const int*   noise  = (const int*)d_in[3];
    const float* lpn    = (const float*)d_in[4];
    float*       out    = (float*)d_out;

    const int rows = in_sizes[0];                              // 6400
    const float norm_c = logf((float)in_sizes[4]) + logf((float)in_sizes[3]);

    zero_kernel<<<1, 1>>>(out);
    dim3 grid(GRID_M, GRID_N);                                 // 50 x 8
    nce_fused_kernel<<<grid, NTHREADS>>>(target, input, embs, noise, lpn,
                                         norm_c, 1.0f / (float)rows, out);
}

// round 12
// speedup vs baseline: 1.5000x; 1.1575x over previous
#include <cuda_runtime.h>
#include <cuda_bf16.h>
#include <math.h>
#include <stdint.h>

// Shapes (fixed): B*N=6400 rows, K=1024 noise, D=64, V=1e6.
#define DIM        64
#define K_NOISE    1024
#define ROWS_TOT   6400
#define MT         128                 // M tile (rows per CTA)
#define NT         128                 // N tile (noise cols per CTA)
#define A_BYTES    (MT * 128)          // 16 KB
#define B_BYTES    (NT * 128)          // 16 KB
#define GRID_M     (ROWS_TOT / MT)     // 50
#define GRID_N     (K_NOISE / NT)      // 8
#define NTHREADS   256
#define TROWS      (MT / GRID_N)       // 16 target rows per CTA
#define LOG2E      1.4426950408889634f

typedef unsigned long long u64;

// ---------------------------------------------------------------------------
// helpers
// ---------------------------------------------------------------------------
static __device__ __forceinline__ uint32_t smem_u32(const void* p) {
    uint32_t a;
    asm("{ .reg .u64 t; cvta.to.shared.u64 t, %1; cvt.u32.u64 %0, t; }"
        : "=r"(a) : "l"(p));
    return a;
}

static __device__ __forceinline__ void ldsm_x4(uint32_t* r, uint32_t addr) {
    asm volatile("ldmatrix.sync.aligned.m8n8.x4.shared.b16 {%0,%1,%2,%3}, [%4];"
                 : "=r"(r[0]), "=r"(r[1]), "=r"(r[2]), "=r"(r[3]) : "r"(addr));
}

static __device__ __forceinline__ void mma16816(float* d, const uint32_t* a,
                                                const uint32_t* b) {
    asm volatile(
        "mma.sync.aligned.m16n8k16.row.col.f32.bf16.bf16.f32 "
        "{%0,%1,%2,%3}, {%4,%5,%6,%7}, {%8,%9}, {%0,%1,%2,%3};"
        : "+f"(d[0]), "+f"(d[1]), "+f"(d[2]), "+f"(d[3])
        : "r"(a[0]), "r"(a[1]), "r"(a[2]), "r"(a[3]), "r"(b[0]), "r"(b[1]));
}

// ---- packed f32x2 ops (Blackwell FFMA2; ptxas never auto-generates) ----
static __device__ __forceinline__ u64 pk(float lo, float hi) {
    u64 r; asm("mov.b64 %0, {%1, %2};" : "=l"(r) : "f"(lo), "f"(hi)); return r;
}
static __device__ __forceinline__ float2 upk(u64 v) {
    float2 f; asm("mov.b64 {%0, %1}, %2;" : "=f"(f.x), "=f"(f.y) : "l"(v)); return f;
}
static __device__ __forceinline__ u64 ffma2(u64 a, u64 b, u64 c) {
    u64 d; asm("fma.rn.f32x2 %0, %1, %2, %3;" : "=l"(d) : "l"(a), "l"(b), "l"(c));
    return d;
}
static __device__ __forceinline__ float ex2f_fast(float x) {
    float y; asm("ex2.approx.ftz.f32 %0, %1;" : "=f"(y) : "f"(x)); return y;
}

// Robust softplus for the target term only (x can be any sign/magnitude).
__device__ __forceinline__ float softplus_full(float x)
{
    if (x > 8.0f) return x + __expf(-x);
    float z = __expf(x);
    if (z < 0.015625f) return z * fmaf(z, fmaf(z, 0.33333334f, -0.5f), 1.0f);
    return __logf(1.0f + z);
}

// convert 8 f32 (two float4) -> 8 bf16 packed in a uint4
static __device__ __forceinline__ uint4 pack8_bf16(float4 a, float4 b)
{
    __nv_bfloat162 h0 = __floats2bfloat162_rn(a.x, a.y);
    __nv_bfloat162 h1 = __floats2bfloat162_rn(a.z, a.w);
    __nv_bfloat162 h2 = __floats2bfloat162_rn(b.x, b.y);
    __nv_bfloat162 h3 = __floats2bfloat162_rn(b.z, b.w);
    uint4 p;
    p.x = *(uint32_t*)&h0; p.y = *(uint32_t*)&h1;
    p.z = *(uint32_t*)&h2; p.w = *(uint32_t*)&h3;
    return p;
}

// ---------------------------------------------------------------------------
// Tiny init kernel: zero the scalar output (stream-ordered before main).
// ---------------------------------------------------------------------------
__global__ void zero_kernel(float* __restrict__ d_out) { d_out[0] = 0.0f; }

// ---------------------------------------------------------------------------
// Fused NCE kernel: one CTA = 128 rows x 128 noise via mma.sync bf16.
//   grid = (50, 8) = 400 CTAs, 256 threads / 8 warps in 4(M) x 2(N);
//   each warp 32x64 as two 32-col passes. Max-MLP staging; target gather
//   split around the mainloop. Epilogue in packed f32x2 (noise softplus
//   ~= z - z^2/2 with z = 2^(s*log2e + nc), nc = -(c*log2e) from smem).
// ---------------------------------------------------------------------------
__global__ void __launch_bounds__(NTHREADS, 3)
nce_fused_kernel(const int* __restrict__ target,
                 const float* __restrict__ input,
                 const float* __restrict__ embs,
                 const int* __restrict__ noise_samples,
                 const float* __restrict__ logprob_noise,
                 float norm_c, float inv_rows, float* __restrict__ d_out)
{
    __shared__ __align__(1024) char s_a[A_BYTES];   // 16 KB A (bf16 SW128)
    __shared__ __align__(1024) char s_b[B_BYTES];   // 16 KB B (bf16 SW128)
    __shared__ __align__(8) float s_c[NT];          // -(c_k * log2e)
    __shared__ float s_red[8];

    const int tid    = threadIdx.x;
    const int lane   = tid & 31;
    const int wid    = tid >> 5;
    const int warp_m = wid & 3;        // 4 warps over M: 32 rows each
    const int warp_n = wid >> 2;       // 2 warps over N: 64 cols each
    const int bm     = blockIdx.x;
    const int bn     = blockIdx.y;

    // ---- early: kick off the target-index load (16 rows per CTA) ----
    int tgt_idx = 0;
    const bool has_tgt = (tid < TROWS);
    const int  trow = bm * MT + bn * TROWS + tid;
    if (has_tgt) tgt_idx = __ldg(&target[trow]);    // arrives during staging

    // ---- staging addresses (thread-invariant swizzle part) ----
    const int rgrp = tid >> 3;          // 0..31
    const int cchk = tid & 7;
    const uint32_t sw_thread =
        (uint32_t)rgrp * 128 + ((uint32_t)((rgrp & 7) ^ cchk) << 4);

    // --- issue ALL staging loads first (max MLP), then convert+store ---
    float4 a0[4], a1[4];                 // A: 4 chunks (rows rgrp + i*32)
    {
        const float4* src = (const float4*)(input
            + (size_t)(bm * MT + rgrp) * DIM + cchk * 8);
#pragma unroll
        for (int i = 0; i < 4; i++) {
            a0[i] = src[i * 16 * DIM / 4 * 2];      // i*32 rows = i*32*64 f32
            a1[i] = src[i * 16 * DIM / 4 * 2 + 1];
        }
    }
    int nidx[4];
#pragma unroll
    for (int i = 0; i < 4; i++)
        nidx[i] = noise_samples[bn * NT + i * 32 + rgrp];
    float4 b0[4], b1[4];
#pragma unroll
    for (int i = 0; i < 4; i++) {
        const float4* src = (const float4*)(embs + (size_t)nidx[i] * DIM + cchk * 8);
        b0[i] = src[0];
        b1[i] = src[1];
    }
    {
        char* dstA = s_a + sw_thread;
        char* dstB = s_b + sw_thread;
#pragma unroll
        for (int i = 0; i < 4; i++) {
            *(uint4*)(dstA + i * 4096) = pack8_bf16(a0[i], a1[i]);
            *(uint4*)(dstB + i * 4096) = pack8_bf16(b0[i], b1[i]);
        }
    }
    if (tid < NT) {
        int it = noise_samples[bn * NT + tid];
        s_c[tid] = -(norm_c + logprob_noise[it]) * LOG2E;
    }
    __syncthreads();

    // ---- start the dependent target row load NOW; consume after mainloop ----
    float4 te_reg[4];
    float  tgt_lpn = 0.0f;
    if (has_tgt) {
        const float4* te = (const float4*)(embs + (size_t)tgt_idx * DIM);
#pragma unroll
        for (int i = 0; i < 4; i++) te_reg[i] = __ldg(&te[i]);
        tgt_lpn = __ldg(&logprob_noise[tgt_idx]);
    }

    // ---- LDSM base addresses (XOR-folded SW128) ----
    const uint32_t r7 = lane & 7;
    const uint32_t a_base0 = smem_u32(s_a)
        + (((uint32_t)(warp_m * 32 + (lane & 15)) * 128)
           ^ (r7 << 4) ^ ((uint32_t)(lane >> 4) << 4));
    const uint32_t b_base0 = smem_u32(s_b)
        + (((uint32_t)(warp_n * 64 + (lane & 7) + ((lane >> 4) << 3)) * 128)
           ^ (r7 << 4) ^ ((uint32_t)((lane >> 3) & 1) << 4));

    // packed epilogue constants / accumulators
    const u64 L2E2 = pk(LOG2E, LOG2E);
    const u64 MH2  = pk(-0.5f, -0.5f);
    const u64 ONE2 = pk(1.0f, 1.0f);
    u64 acc2a = pk(0.0f, 0.0f);
    u64 acc2b = pk(0.0f, 0.0f);

    // --- two 32-col passes per warp ---
#pragma unroll
    for (int np = 0; np < 2; np++) {
        float acc[2][4][4] = {};
#pragma unroll
        for (int k = 0; k < 4; k++) {           // K = 4 x k16
            uint32_t afr[2][4];
#pragma unroll
            for (int mi = 0; mi < 2; mi++)
                ldsm_x4(afr[mi], (a_base0 + mi * 2048) ^ (k << 5));
            uint32_t bfr[4][2];
#pragma unroll
            for (int nj = 0; nj < 2; nj++) {
                uint32_t b4[4];
                ldsm_x4(b4, (b_base0 + np * 4096 + nj * 2048) ^ (k << 5));
                bfr[nj * 2][0]     = b4[0]; bfr[nj * 2][1]     = b4[1];
                bfr[nj * 2 + 1][0] = b4[2]; bfr[nj * 2 + 1][1] = b4[3];
            }
#pragma unroll
            for (int mi = 0; mi < 2; mi++)
#pragma unroll
                for (int ni = 0; ni < 4; ni++)
                    mma16816(acc[mi][ni], afr[mi], bfr[ni]);
        }
        // packed epilogue: per (mi,ni) two f32x2 lanes share the nc2 addend
#pragma unroll
        for (int ni = 0; ni < 4; ni++) {
            int col = warp_n * 64 + np * 32 + ni * 8 + (lane & 3) * 2;
            const u64 nc2 = *(const u64*)&s_c[col];     // 8B-aligned LDS.64
#pragma unroll
            for (int mi = 0; mi < 2; mi++) {
                float2 t0 = upk(ffma2(pk(acc[mi][ni][0], acc[mi][ni][1]), L2E2, nc2));
                u64 z0 = pk(ex2f_fast(t0.x), ex2f_fast(t0.y));
                acc2a = ffma2(z0, ffma2(z0, MH2, ONE2), acc2a);
                float2 t1 = upk(ffma2(pk(acc[mi][ni][2], acc[mi][ni][3]), L2E2, nc2));
                u64 z1 = pk(ex2f_fast(t1.x), ex2f_fast(t1.y));
                acc2b = ffma2(z1, ffma2(z1, MH2, ONE2), acc2b);
            }
        }
    }
    float2 fa = upk(acc2a), fb = upk(acc2b);
    float local = (fa.x + fa.y) + (fb.x + fb.y);

    // ---- deferred target term (exact f32; loads long since arrived) ----
    if (has_tgt) {
        const float4* ti = (const float4*)(input + (size_t)trow * DIM);
        float acc = 0.0f;
#pragma unroll
        for (int i = 0; i < 4; i++) {
            float4 x = ti[i], e = te_reg[i];
            acc = fmaf(x.x, e.x, fmaf(x.y, e.y, fmaf(x.z, e.z, fmaf(x.w, e.w, acc))));
        }
        float xt = acc - norm_c - tgt_lpn;
        local += softplus_full(-xt);
    }

    // --- block reduction + one atomicAdd per CTA ---
#pragma unroll
    for (int o = 16; o; o >>= 1)
        local += __shfl_xor_sync(0xffffffffu, local, o);
    if (lane == 0) s_red[wid] = local;
    __syncthreads();
    if (tid == 0) {
        float s = 0.0f;
#pragma unroll
        for (int w = 0; w < 8; w++) s += s_red[w];
        atomicAdd(d_out, s * inv_rows);
    }
}

// ---------------------------------------------------------------------------
// Launch. Inputs (metadata order): target i32[6400], input f32[6400*64],
// embs f32[1e6*64], noise_samples i32[1024], logprob_noise f32[1e6].
// Output: f32[1] (mean loss).
// ---------------------------------------------------------------------------
extern "C" void kernel_launch(void* const* d_in, const int* in_sizes, int n_in,
                              void* d_out, int out_size)
{
    const int*   target = (const int*)d_in[0];
    const float* input  = (const float*)d_in[1];
    const float* embs   = (const float*)d_in[2];
    const int*   noise  = (const int*)d_in[3];
    const float* lpn    = (const float*)d_in[4];
    float*       out    = (float*)d_out;

    const int rows = in_sizes[0];                              // 6400
    const float norm_c = logf((float)in_sizes[4]) + logf((float)in_sizes[3]);

    zero_kernel<<<1, 1>>>(out);
    dim3 grid(GRID_M, GRID_N);                                 // 50 x 8
    nce_fused_kernel<<<grid, NTHREADS>>>(target, input, embs, noise, lpn,
                                         norm_c, 1.0f / (float)rows, out);
}